// round 1
// baseline (speedup 1.0000x reference)
#include <cuda_runtime.h>

#define BATCH 131072
#define NL    24

__global__ __launch_bounds__(256)
void fk_kernel(const float* __restrict__ q,
               const float* __restrict__ axes,
               const float* __restrict__ t_fix,
               float* __restrict__ out) {
    __shared__ float s_ax[NL][3];
    __shared__ float s_tf[NL][3];

    int tid = threadIdx.x;
    if (tid < NL) {
        float ax = axes[tid * 3 + 0];
        float ay = axes[tid * 3 + 1];
        float az = axes[tid * 3 + 2];
        float inv = rsqrtf(ax * ax + ay * ay + az * az);
        s_ax[tid][0] = ax * inv;
        s_ax[tid][1] = ay * inv;
        s_ax[tid][2] = az * inv;
        s_tf[tid][0] = t_fix[tid * 3 + 0];
        s_tf[tid][1] = t_fix[tid * 3 + 1];
        s_tf[tid][2] = t_fix[tid * 3 + 2];
    }
    __syncthreads();

    int b = blockIdx.x * blockDim.x + tid;
    if (b >= BATCH) return;

    // Load this batch row of q: 24 floats, 96 B, 16 B aligned -> 6x LDG.128
    float qv[NL];
    {
        const float4* qr = reinterpret_cast<const float4*>(q + (size_t)b * NL);
        #pragma unroll
        for (int i = 0; i < NL / 4; i++) {
            float4 v = qr[i];
            qv[i * 4 + 0] = v.x;
            qv[i * 4 + 1] = v.y;
            qv[i * 4 + 2] = v.z;
            qv[i * 4 + 3] = v.w;
        }
    }

    // Running pose
    float R00 = 1.f, R01 = 0.f, R02 = 0.f;
    float R10 = 0.f, R11 = 1.f, R12 = 0.f;
    float R20 = 0.f, R21 = 0.f, R22 = 1.f;
    float t0 = 0.f, t1 = 0.f, t2 = 0.f;

    float4* o = reinterpret_cast<float4*>(out + (size_t)b * NL * 16);

    #pragma unroll
    for (int l = 0; l < NL; l++) {
        float s, c;
        __sincosf(qv[l], &s, &c);
        float C = 1.f - c;

        float ax = s_ax[l][0], ay = s_ax[l][1], az = s_ax[l][2];

        // Rodrigues: Rj = c*I + s*K + C*(a a^T)
        float j00 = fmaf(C * ax, ax, c);
        float j01 = fmaf(C * ax, ay, -s * az);
        float j02 = fmaf(C * ax, az,  s * ay);
        float j10 = fmaf(C * ay, ax,  s * az);
        float j11 = fmaf(C * ay, ay, c);
        float j12 = fmaf(C * ay, az, -s * ax);
        float j20 = fmaf(C * az, ax, -s * ay);
        float j21 = fmaf(C * az, ay,  s * ax);
        float j22 = fmaf(C * az, az, c);

        // Translation first (uses parent R): t += R @ tf
        float tf0 = s_tf[l][0], tf1 = s_tf[l][1], tf2 = s_tf[l][2];
        t0 = fmaf(R00, tf0, fmaf(R01, tf1, fmaf(R02, tf2, t0)));
        t1 = fmaf(R10, tf0, fmaf(R11, tf1, fmaf(R12, tf2, t1)));
        t2 = fmaf(R20, tf0, fmaf(R21, tf1, fmaf(R22, tf2, t2)));

        // R = R @ Rj
        float n00 = fmaf(R00, j00, fmaf(R01, j10, R02 * j20));
        float n01 = fmaf(R00, j01, fmaf(R01, j11, R02 * j21));
        float n02 = fmaf(R00, j02, fmaf(R01, j12, R02 * j22));
        float n10 = fmaf(R10, j00, fmaf(R11, j10, R12 * j20));
        float n11 = fmaf(R10, j01, fmaf(R11, j11, R12 * j21));
        float n12 = fmaf(R10, j02, fmaf(R11, j12, R12 * j22));
        float n20 = fmaf(R20, j00, fmaf(R21, j10, R22 * j20));
        float n21 = fmaf(R20, j01, fmaf(R21, j11, R22 * j21));
        float n22 = fmaf(R20, j02, fmaf(R21, j12, R22 * j22));
        R00 = n00; R01 = n01; R02 = n02;
        R10 = n10; R11 = n11; R12 = n12;
        R20 = n20; R21 = n21; R22 = n22;

        // Store 4x4 pose: rows [R | t], bottom [0 0 0 1]
        o[l * 4 + 0] = make_float4(R00, R01, R02, t0);
        o[l * 4 + 1] = make_float4(R10, R11, R12, t1);
        o[l * 4 + 2] = make_float4(R20, R21, R22, t2);
        o[l * 4 + 3] = make_float4(0.f, 0.f, 0.f, 1.f);
    }
}

extern "C" void kernel_launch(void* const* d_in, const int* in_sizes, int n_in,
                              void* d_out, int out_size) {
    const float* q     = (const float*)d_in[0];
    // d_in[1] = qd, unused by the reference computation
    const float* axes  = (const float*)d_in[2];
    const float* t_fix = (const float*)d_in[3];
    float* out = (float*)d_out;

    dim3 block(256);
    dim3 grid((BATCH + 255) / 256);
    fk_kernel<<<grid, block>>>(q, axes, t_fix, out);
}

// round 2
// speedup vs baseline: 4.5230x; 4.5230x over previous
#include <cuda_runtime.h>

#define BATCH 131072
#define NL    24
#define BT    64          // threads (batches) per block
#define PH    12          // links per staging phase
#define STRIDE 37         // float4 slots per batch in smem (36 data + 1 pad)

__global__ __launch_bounds__(BT)
void fk_kernel(const float* __restrict__ q,
               const float* __restrict__ axes,
               const float* __restrict__ t_fix,
               float* __restrict__ out) {
    __shared__ float  s_ax[NL][3];
    __shared__ float  s_tf[NL][3];
    __shared__ float4 stage[BT * STRIDE];   // 37888 B

    int tid = threadIdx.x;
    if (tid < NL) {
        float ax = axes[tid * 3 + 0];
        float ay = axes[tid * 3 + 1];
        float az = axes[tid * 3 + 2];
        float inv = rsqrtf(ax * ax + ay * ay + az * az);
        s_ax[tid][0] = ax * inv;
        s_ax[tid][1] = ay * inv;
        s_ax[tid][2] = az * inv;
        s_tf[tid][0] = t_fix[tid * 3 + 0];
        s_tf[tid][1] = t_fix[tid * 3 + 1];
        s_tf[tid][2] = t_fix[tid * 3 + 2];
    }
    __syncthreads();

    int b = blockIdx.x * BT + tid;

    // Load this batch's 24 joint angles: 6x LDG.128, coalesced.
    float qv[NL];
    {
        const float4* qr = reinterpret_cast<const float4*>(q + (size_t)b * NL);
        #pragma unroll
        for (int i = 0; i < NL / 4; i++) {
            float4 v = qr[i];
            qv[i * 4 + 0] = v.x;
            qv[i * 4 + 1] = v.y;
            qv[i * 4 + 2] = v.z;
            qv[i * 4 + 3] = v.w;
        }
    }

    // Running pose (registers)
    float R00 = 1.f, R01 = 0.f, R02 = 0.f;
    float R10 = 0.f, R11 = 1.f, R12 = 0.f;
    float R20 = 0.f, R21 = 0.f, R22 = 1.f;
    float t0 = 0.f, t1 = 0.f, t2 = 0.f;

    float4* gout = reinterpret_cast<float4*>(out);
    const long gbase = (long)blockIdx.x * BT * 96;   // float4 units; 96 per batch

    #pragma unroll
    for (int p = 0; p < 2; p++) {
        // ---- compute PH links, stage pose rows in smem ----
        #pragma unroll
        for (int ll = 0; ll < PH; ll++) {
            int l = p * PH + ll;
            float s, c;
            __sincosf(qv[l], &s, &c);
            float C = 1.f - c;

            float ax = s_ax[l][0], ay = s_ax[l][1], az = s_ax[l][2];

            // Rodrigues: Rj = c*I + s*K + (1-c)*(a a^T)
            float j00 = fmaf(C * ax, ax, c);
            float j01 = fmaf(C * ax, ay, -s * az);
            float j02 = fmaf(C * ax, az,  s * ay);
            float j10 = fmaf(C * ay, ax,  s * az);
            float j11 = fmaf(C * ay, ay, c);
            float j12 = fmaf(C * ay, az, -s * ax);
            float j20 = fmaf(C * az, ax, -s * ay);
            float j21 = fmaf(C * az, ay,  s * ax);
            float j22 = fmaf(C * az, az, c);

            // t += R @ tf (parent R)
            float tf0 = s_tf[l][0], tf1 = s_tf[l][1], tf2 = s_tf[l][2];
            t0 = fmaf(R00, tf0, fmaf(R01, tf1, fmaf(R02, tf2, t0)));
            t1 = fmaf(R10, tf0, fmaf(R11, tf1, fmaf(R12, tf2, t1)));
            t2 = fmaf(R20, tf0, fmaf(R21, tf1, fmaf(R22, tf2, t2)));

            // R = R @ Rj
            float n00 = fmaf(R00, j00, fmaf(R01, j10, R02 * j20));
            float n01 = fmaf(R00, j01, fmaf(R01, j11, R02 * j21));
            float n02 = fmaf(R00, j02, fmaf(R01, j12, R02 * j22));
            float n10 = fmaf(R10, j00, fmaf(R11, j10, R12 * j20));
            float n11 = fmaf(R10, j01, fmaf(R11, j11, R12 * j21));
            float n12 = fmaf(R10, j02, fmaf(R11, j12, R12 * j22));
            float n20 = fmaf(R20, j00, fmaf(R21, j10, R22 * j20));
            float n21 = fmaf(R20, j01, fmaf(R21, j11, R22 * j21));
            float n22 = fmaf(R20, j02, fmaf(R21, j12, R22 * j22));
            R00 = n00; R01 = n01; R02 = n02;
            R10 = n10; R11 = n11; R12 = n12;
            R20 = n20; R21 = n21; R22 = n22;

            // Stage 3 pose rows (bottom row synthesized at writeback).
            int sbase = tid * STRIDE + ll * 3;
            stage[sbase + 0] = make_float4(R00, R01, R02, t0);
            stage[sbase + 1] = make_float4(R10, R11, R12, t1);
            stage[sbase + 2] = make_float4(R20, R21, R22, t2);
        }
        __syncthreads();

        // ---- coalesced writeback: BT batches x 48 float4 (12 links * 4 rows) ----
        #pragma unroll 8
        for (int i = tid; i < BT * 48; i += BT) {
            int bl = i / 48;
            int j  = i - bl * 48;        // row chunk within this phase's region
            float4 v;
            if ((j & 3) == 3) {
                v = make_float4(0.f, 0.f, 0.f, 1.f);
            } else {
                v = stage[bl * STRIDE + (j >> 2) * 3 + (j & 3)];
            }
            gout[gbase + (long)bl * 96 + p * 48 + j] = v;
        }
        __syncthreads();
    }
}

extern "C" void kernel_launch(void* const* d_in, const int* in_sizes, int n_in,
                              void* d_out, int out_size) {
    const float* q     = (const float*)d_in[0];
    // d_in[1] = qd, unused by the reference computation
    const float* axes  = (const float*)d_in[2];
    const float* t_fix = (const float*)d_in[3];
    float* out = (float*)d_out;

    dim3 block(BT);
    dim3 grid(BATCH / BT);
    fk_kernel<<<grid, block>>>(q, axes, t_fix, out);
}

// round 3
// speedup vs baseline: 4.6664x; 1.0317x over previous
#include <cuda_runtime.h>

#define BATCH 131072
#define NL    24
#define BT    128         // threads (batches) per block
#define PH    4           // links per staging phase
#define NPHASE (NL / PH)  // 6
#define STRIDE 13         // float4 slots per batch in smem (12 data + 1 pad)

__global__ __launch_bounds__(BT, 8)
void fk_kernel(const float* __restrict__ q,
               const float* __restrict__ axes,
               const float* __restrict__ t_fix,
               float* __restrict__ out) {
    __shared__ float  s_ax[NL][3];
    __shared__ float  s_tf[NL][3];
    __shared__ float4 stage[BT * STRIDE];   // 26624 B

    int tid = threadIdx.x;
    if (tid < NL) {
        float ax = axes[tid * 3 + 0];
        float ay = axes[tid * 3 + 1];
        float az = axes[tid * 3 + 2];
        float inv = rsqrtf(ax * ax + ay * ay + az * az);
        s_ax[tid][0] = ax * inv;
        s_ax[tid][1] = ay * inv;
        s_ax[tid][2] = az * inv;
        s_tf[tid][0] = t_fix[tid * 3 + 0];
        s_tf[tid][1] = t_fix[tid * 3 + 1];
        s_tf[tid][2] = t_fix[tid * 3 + 2];
    }
    __syncthreads();

    int b = blockIdx.x * BT + tid;
    const float4* qr = reinterpret_cast<const float4*>(q + (size_t)b * NL);

    // Running pose (registers)
    float R00 = 1.f, R01 = 0.f, R02 = 0.f;
    float R10 = 0.f, R11 = 1.f, R12 = 0.f;
    float R20 = 0.f, R21 = 0.f, R22 = 1.f;
    float t0 = 0.f, t1 = 0.f, t2 = 0.f;

    float4* gout = reinterpret_cast<float4*>(out);
    const long gbase = (long)blockIdx.x * BT * 96;   // float4 units; 96 per batch

    // Loop-invariant writeback mapping: each thread owns one of 16 row-slots
    // across 8 batches per iteration.
    const int j      = tid & 15;            // float4 index within phase region
    const int bl0    = tid >> 4;            // first batch this thread services
    const bool isbot = (j & 3) == 3;        // bottom row [0,0,0,1]
    const int  slot  = (j >> 2) * 3 + (j & 3);  // stage slot (unused if isbot)
    const float4 BOT = make_float4(0.f, 0.f, 0.f, 1.f);

    float4 qnext = qr[0];

    #pragma unroll
    for (int p = 0; p < NPHASE; p++) {
        float4 qc = qnext;
        if (p < NPHASE - 1) qnext = qr[p + 1];
        float qv4[PH] = {qc.x, qc.y, qc.z, qc.w};

        // ---- compute PH links, stage pose rows in smem ----
        #pragma unroll
        for (int ll = 0; ll < PH; ll++) {
            int l = p * PH + ll;
            float s, c;
            __sincosf(qv4[ll], &s, &c);
            float C = 1.f - c;

            float ax = s_ax[l][0], ay = s_ax[l][1], az = s_ax[l][2];

            // Rodrigues: Rj = c*I + s*K + (1-c)*(a a^T)
            float j00 = fmaf(C * ax, ax, c);
            float j01 = fmaf(C * ax, ay, -s * az);
            float j02 = fmaf(C * ax, az,  s * ay);
            float j10 = fmaf(C * ay, ax,  s * az);
            float j11 = fmaf(C * ay, ay, c);
            float j12 = fmaf(C * ay, az, -s * ax);
            float j20 = fmaf(C * az, ax, -s * ay);
            float j21 = fmaf(C * az, ay,  s * ax);
            float j22 = fmaf(C * az, az, c);

            // t += R @ tf (parent R)
            float tf0 = s_tf[l][0], tf1 = s_tf[l][1], tf2 = s_tf[l][2];
            t0 = fmaf(R00, tf0, fmaf(R01, tf1, fmaf(R02, tf2, t0)));
            t1 = fmaf(R10, tf0, fmaf(R11, tf1, fmaf(R12, tf2, t1)));
            t2 = fmaf(R20, tf0, fmaf(R21, tf1, fmaf(R22, tf2, t2)));

            // R = R @ Rj
            float n00 = fmaf(R00, j00, fmaf(R01, j10, R02 * j20));
            float n01 = fmaf(R00, j01, fmaf(R01, j11, R02 * j21));
            float n02 = fmaf(R00, j02, fmaf(R01, j12, R02 * j22));
            float n10 = fmaf(R10, j00, fmaf(R11, j10, R12 * j20));
            float n11 = fmaf(R10, j01, fmaf(R11, j11, R12 * j21));
            float n12 = fmaf(R10, j02, fmaf(R11, j12, R12 * j22));
            float n20 = fmaf(R20, j00, fmaf(R21, j10, R22 * j20));
            float n21 = fmaf(R20, j01, fmaf(R21, j11, R22 * j21));
            float n22 = fmaf(R20, j02, fmaf(R21, j12, R22 * j22));
            R00 = n00; R01 = n01; R02 = n02;
            R10 = n10; R11 = n11; R12 = n12;
            R20 = n20; R21 = n21; R22 = n22;

            int sbase = tid * STRIDE + ll * 3;
            stage[sbase + 0] = make_float4(R00, R01, R02, t0);
            stage[sbase + 1] = make_float4(R10, R11, R12, t1);
            stage[sbase + 2] = make_float4(R20, R21, R22, t2);
        }
        __syncthreads();

        // ---- coalesced writeback: BT batches x 16 float4 (4 links * 4 rows) ----
        #pragma unroll
        for (int k = 0; k < 16; k++) {
            int bl = bl0 + k * 8;
            float4 v = isbot ? BOT : stage[bl * STRIDE + slot];
            gout[gbase + (long)bl * 96 + p * 16 + j] = v;
        }
        __syncthreads();
    }
}

extern "C" void kernel_launch(void* const* d_in, const int* in_sizes, int n_in,
                              void* d_out, int out_size) {
    const float* q     = (const float*)d_in[0];
    // d_in[1] = qd, unused by the reference computation
    const float* axes  = (const float*)d_in[2];
    const float* t_fix = (const float*)d_in[3];
    float* out = (float*)d_out;

    dim3 block(BT);
    dim3 grid(BATCH / BT);
    fk_kernel<<<grid, block>>>(q, axes, t_fix, out);
}

// round 4
// speedup vs baseline: 5.3579x; 1.1482x over previous
#include <cuda_runtime.h>

#define BATCH 131072
#define NL    24
#define BT    64          // threads (batches) per block
#define PH    2           // links per staging phase
#define NPHASE (NL / PH)  // 12
#define STRIDE 7          // float4 slots per batch per buffer (6 data + 1 pad)

__global__ __launch_bounds__(BT)
void fk_kernel(const float* __restrict__ q,
               const float* __restrict__ axes,
               const float* __restrict__ t_fix,
               float* __restrict__ out) {
    __shared__ float  s_ax[NL][3];
    __shared__ float  s_tf[NL][3];
    __shared__ float4 stage[2][BT * STRIDE];   // 2 x 7168 B

    int tid = threadIdx.x;
    if (tid < NL) {
        float ax = axes[tid * 3 + 0];
        float ay = axes[tid * 3 + 1];
        float az = axes[tid * 3 + 2];
        float inv = rsqrtf(ax * ax + ay * ay + az * az);
        s_ax[tid][0] = ax * inv;
        s_ax[tid][1] = ay * inv;
        s_ax[tid][2] = az * inv;
        s_tf[tid][0] = t_fix[tid * 3 + 0];
        s_tf[tid][1] = t_fix[tid * 3 + 1];
        s_tf[tid][2] = t_fix[tid * 3 + 2];
    }
    __syncthreads();

    int b = blockIdx.x * BT + tid;
    const float2* qr = reinterpret_cast<const float2*>(q + (size_t)b * NL);

    // Running pose (registers)
    float R00 = 1.f, R01 = 0.f, R02 = 0.f;
    float R10 = 0.f, R11 = 1.f, R12 = 0.f;
    float R20 = 0.f, R21 = 0.f, R22 = 1.f;
    float t0 = 0.f, t1 = 0.f, t2 = 0.f;

    float4* gout = reinterpret_cast<float4*>(out);
    const long gbase = (long)blockIdx.x * BT * 96;   // float4 units; 96 per batch

    // Loop-invariant writeback mapping: 8 float4 per batch per phase.
    const int  j     = tid & 7;              // float4 index within phase region
    const int  bl0   = tid >> 3;             // first batch this thread services
    const bool isbot = (j & 3) == 3;         // bottom row [0,0,0,1]
    const int  slot  = (j >> 2) * 3 + (j & 3);
    const float4 BOT = make_float4(0.f, 0.f, 0.f, 1.f);

    float2 qnext = qr[0];

    #pragma unroll
    for (int p = 0; p < NPHASE; p++) {
        float2 qc = qnext;
        if (p < NPHASE - 1) qnext = qr[p + 1];
        float qv2[PH] = {qc.x, qc.y};

        float4* buf = stage[p & 1];

        // ---- compute PH links, stage pose rows into this phase's buffer ----
        #pragma unroll
        for (int ll = 0; ll < PH; ll++) {
            int l = p * PH + ll;
            float s, c;
            __sincosf(qv2[ll], &s, &c);
            float C = 1.f - c;

            float ax = s_ax[l][0], ay = s_ax[l][1], az = s_ax[l][2];

            // Rodrigues: Rj = c*I + s*K + (1-c)*(a a^T)
            float j00 = fmaf(C * ax, ax, c);
            float j01 = fmaf(C * ax, ay, -s * az);
            float j02 = fmaf(C * ax, az,  s * ay);
            float j10 = fmaf(C * ay, ax,  s * az);
            float j11 = fmaf(C * ay, ay, c);
            float j12 = fmaf(C * ay, az, -s * ax);
            float j20 = fmaf(C * az, ax, -s * ay);
            float j21 = fmaf(C * az, ay,  s * ax);
            float j22 = fmaf(C * az, az, c);

            // t += R @ tf (parent R)
            float tf0 = s_tf[l][0], tf1 = s_tf[l][1], tf2 = s_tf[l][2];
            t0 = fmaf(R00, tf0, fmaf(R01, tf1, fmaf(R02, tf2, t0)));
            t1 = fmaf(R10, tf0, fmaf(R11, tf1, fmaf(R12, tf2, t1)));
            t2 = fmaf(R20, tf0, fmaf(R21, tf1, fmaf(R22, tf2, t2)));

            // R = R @ Rj
            float n00 = fmaf(R00, j00, fmaf(R01, j10, R02 * j20));
            float n01 = fmaf(R00, j01, fmaf(R01, j11, R02 * j21));
            float n02 = fmaf(R00, j02, fmaf(R01, j12, R02 * j22));
            float n10 = fmaf(R10, j00, fmaf(R11, j10, R12 * j20));
            float n11 = fmaf(R10, j01, fmaf(R11, j11, R12 * j21));
            float n12 = fmaf(R10, j02, fmaf(R11, j12, R12 * j22));
            float n20 = fmaf(R20, j00, fmaf(R21, j10, R22 * j20));
            float n21 = fmaf(R20, j01, fmaf(R21, j11, R22 * j21));
            float n22 = fmaf(R20, j02, fmaf(R21, j12, R22 * j22));
            R00 = n00; R01 = n01; R02 = n02;
            R10 = n10; R11 = n11; R12 = n12;
            R20 = n20; R21 = n21; R22 = n22;

            int sbase = tid * STRIDE + ll * 3;
            buf[sbase + 0] = make_float4(R00, R01, R02, t0);
            buf[sbase + 1] = make_float4(R10, R11, R12, t1);
            buf[sbase + 2] = make_float4(R20, R21, R22, t2);
        }
        __syncthreads();   // buf[p&1] ready; also guarantees writeback(p-1) done

        // ---- coalesced writeback: BT batches x 8 float4 (2 links * 4 rows) ----
        // Overlaps (across warps) with compute of phase p+1, which uses the
        // other buffer. No trailing sync needed: any thread reaching
        // compute(p+2) has passed sync(p+1), which follows writeback(p) in
        // every thread's program order.
        #pragma unroll
        for (int k = 0; k < 8; k++) {
            int bl = bl0 + k * 8;
            float4 v = isbot ? BOT : buf[bl * STRIDE + slot];
            __stcs(&gout[gbase + (long)bl * 96 + p * 8 + j], v);
        }
    }
}

extern "C" void kernel_launch(void* const* d_in, const int* in_sizes, int n_in,
                              void* d_out, int out_size) {
    const float* q     = (const float*)d_in[0];
    // d_in[1] = qd, unused by the reference computation
    const float* axes  = (const float*)d_in[2];
    const float* t_fix = (const float*)d_in[3];
    float* out = (float*)d_out;

    dim3 block(BT);
    dim3 grid(BATCH / BT);
    fk_kernel<<<grid, block>>>(q, axes, t_fix, out);
}